// round 3
// baseline (speedup 1.0000x reference)
#include <cuda_runtime.h>

#define NSUB 20
#define NB 3
#define NE 500
#define NI 200
#define T_SYN 201
#define TPAD 208          // taps padded to multiple of 8 with zeros
#define TMAX 100000

#define TT 128            // conv output rows per block
#define HALO TPAD         // 208 history rows (taps 201..207 are zero)
#define XROWS (TT + HALO) // 336
#define RPAD 337          // 337 % 32 = 17 (odd) -> conflict-free column access

// Scratch (static device globals: allocation is forbidden)
__device__ float g_kern[2 * NSUB * TPAD];          // [c][s][t], zero-padded taps
__device__ float g_X[(size_t)TMAX * 40];           // [t][c*20+s] GEMM intermediate

// ---------------------------------------------------------------------------
// K0: build the alpha-function kernel bank  kern[c][s][t]
// ---------------------------------------------------------------------------
__global__ void k0_kernels(const float* __restrict__ K_syn,
                           const float* __restrict__ tau_syn,
                           const float* __restrict__ delta_syn) {
    int idx = blockIdx.x * blockDim.x + threadIdx.x;
    if (idx >= 2 * NSUB * TPAD) return;
    int t = idx % TPAD;
    int s = (idx / TPAD) % NSUB;
    int c = idx / (TPAD * NSUB);
    float val = 0.f;
    if (t < T_SYN) {
        float ts = (float)t - delta_syn[s * 2 + c];
        ts = fmaxf(ts, 0.f);
        #pragma unroll
        for (int b = 0; b < NB; b++) {
            float tau = expf(tau_syn[b * 2 + c]);
            float tt = ts / tau;
            val += K_syn[s * NB * 2 + b * 2 + c] * tt * expf(-tt);
        }
    }
    g_kern[idx] = val;   // t in [201,208) stays 0
}

// ---------------------------------------------------------------------------
// K1: tall-skinny GEMM.  X[t][ph*20+s] = sum_k S[t][k] * C[s][k]
// 128 threads handle 256 rows (2 rows/thread), k-chunks of 16.
// C chunk read as broadcast float4 -> 1 LDS.128 per 8 FMAs (FFMA-bound).
// ---------------------------------------------------------------------------
__global__ __launch_bounds__(128) void k1_gemm(const float* __restrict__ Se,
                                               const float* __restrict__ Si,
                                               const float* __restrict__ Ce,
                                               const float* __restrict__ Ci,
                                               int T) {
    __shared__ float  Ssh[256][17];     // pad 17 -> conflict-free row reads
    __shared__ float4 Csh4[NSUB][4];    // [s][k4], 16 taps per chunk
    float* Csh = (float*)Csh4;

    int tid = threadIdx.x;
    int rbase = blockIdx.x * 256;

    #pragma unroll
    for (int ph = 0; ph < 2; ph++) {
        const float* S = ph ? Si : Se;
        const float* C = ph ? Ci : Ce;
        const int NC = ph ? NI : NE;

        float acc0[NSUB], acc1[NSUB];
        #pragma unroll
        for (int s = 0; s < NSUB; s++) { acc0[s] = 0.f; acc1[s] = 0.f; }

        for (int kb = 0; kb < NC; kb += 16) {
            __syncthreads();   // protect previous chunk's reads
            // load C chunk (320 floats)
            #pragma unroll
            for (int idx = tid; idx < NSUB * 16; idx += 128) {
                int s = idx >> 4, k = idx & 15;
                Csh[idx] = (kb + k < NC) ? C[s * NC + kb + k] : 0.f;
            }
            // load S tile (256 x 16, coalesced 64B runs per row)
            #pragma unroll
            for (int j = 0; j < 32; j++) {
                int idx = j * 128 + tid;
                int r = idx >> 4, k = idx & 15;
                int row = rbase + r;
                Ssh[r][k] = (row < T && kb + k < NC) ? S[(size_t)row * NC + kb + k] : 0.f;
            }
            __syncthreads();

            #pragma unroll
            for (int k4 = 0; k4 < 4; k4++) {
                float a0[4], a1[4];
                #pragma unroll
                for (int m = 0; m < 4; m++) {
                    a0[m] = Ssh[tid][k4 * 4 + m];
                    a1[m] = Ssh[tid + 128][k4 * 4 + m];
                }
                #pragma unroll
                for (int s = 0; s < NSUB; s++) {
                    float4 c = Csh4[s][k4];
                    acc0[s] = fmaf(a0[0], c.x, acc0[s]);
                    acc0[s] = fmaf(a0[1], c.y, acc0[s]);
                    acc0[s] = fmaf(a0[2], c.z, acc0[s]);
                    acc0[s] = fmaf(a0[3], c.w, acc0[s]);
                    acc1[s] = fmaf(a1[0], c.x, acc1[s]);
                    acc1[s] = fmaf(a1[1], c.y, acc1[s]);
                    acc1[s] = fmaf(a1[2], c.z, acc1[s]);
                    acc1[s] = fmaf(a1[3], c.w, acc1[s]);
                }
            }
        }

        int row0 = rbase + tid, row1 = row0 + 128;
        if (row0 < T) {
            float4* d = (float4*)&g_X[(size_t)row0 * 40 + ph * 20];
            #pragma unroll
            for (int q = 0; q < 5; q++)
                d[q] = make_float4(acc0[4*q], acc0[4*q+1], acc0[4*q+2], acc0[4*q+3]);
        }
        if (row1 < T) {
            float4* d = (float4*)&g_X[(size_t)row1 * 40 + ph * 20];
            #pragma unroll
            for (int q = 0; q < 5; q++)
                d[q] = make_float4(acc1[4*q], acc1[4*q+1], acc1[4*q+2], acc1[4*q+3]);
        }
    }
}

// ---------------------------------------------------------------------------
// K2: depthwise causal FIR.  out[t][s] = sum_c sum_k kern[c][s][k] * X[t-k][c*20+s]
// Block: dim3(20,16) = 320 threads. Thread (s, tg) computes 8 consecutive t.
// Register blocking 8 outputs x 8 taps: 23 LDS per 64 FMA.
// ---------------------------------------------------------------------------
__global__ __launch_bounds__(320) void k2_conv(float* __restrict__ out, int T) {
    extern __shared__ float sm[];
    float* Xsh = sm;                   // [40][RPAD], time-transposed
    float* ksh = sm + 40 * RPAD;       // [40][TPAD]

    int tid = threadIdx.y * 20 + threadIdx.x;
    int t0 = blockIdx.x * TT;

    for (int idx = tid; idx < 40 * TPAD; idx += 320)
        ksh[idx] = g_kern[idx];

    for (int idx = tid; idx < XROWS * 40; idx += 320) {
        int j = idx / 40, c2 = idx - j * 40;
        int tg = t0 - HALO + j;
        float v = (tg >= 0 && tg < T) ? g_X[(size_t)tg * 40 + c2] : 0.f;
        Xsh[c2 * RPAD + j] = v;        // conflict-free (stride 337)
    }
    __syncthreads();

    int s = threadIdx.x, tg = threadIdx.y;
    float acc[8];
    #pragma unroll
    for (int r = 0; r < 8; r++) acc[r] = 0.f;

    int base_out = HALO + tg * 8;      // tile row of this thread's first output

    #pragma unroll
    for (int c = 0; c < 2; c++) {
        const float* xc = Xsh + (c * 20 + s) * RPAD;
        const float* kk = ksh + (c * 20 + s) * TPAD;
        #pragma unroll 2
        for (int kb = 0; kb < TPAD; kb += 8) {
            float kv[8];
            #pragma unroll
            for (int m = 0; m < 8; m++) kv[m] = kk[kb + m];
            float xw[15];
            int b = base_out - kb - 7;  // >= 1 always (taps 201..207 are zero)
            #pragma unroll
            for (int m = 0; m < 15; m++) xw[m] = xc[b + m];
            #pragma unroll
            for (int r = 0; r < 8; r++) {
                #pragma unroll
                for (int k = 0; k < 8; k++)
                    acc[r] = fmaf(kv[k], xw[r - k + 7], acc[r]);
            }
        }
    }

    #pragma unroll
    for (int r = 0; r < 8; r++) {
        int t = t0 + tg * 8 + r;
        if (t < T) out[(size_t)t * 20 + s] = acc[r];
    }
}

// ---------------------------------------------------------------------------
extern "C" void kernel_launch(void* const* d_in, const int* in_sizes, int n_in,
                              void* d_out, int out_size) {
    const float* Se        = (const float*)d_in[0];
    const float* Si        = (const float*)d_in[1];
    const float* Ce        = (const float*)d_in[2];
    const float* Ci        = (const float*)d_in[3];
    const float* K_syn     = (const float*)d_in[4];
    const float* tau_syn   = (const float*)d_in[5];
    const float* delta_syn = (const float*)d_in[6];
    float* out = (float*)d_out;

    int T = in_sizes[0] / NE;
    if (T > TMAX) T = TMAX;

    k0_kernels<<<(2 * NSUB * TPAD + 255) / 256, 256>>>(K_syn, tau_syn, delta_syn);
    k1_gemm<<<(T + 255) / 256, 128>>>(Se, Si, Ce, Ci, T);

    int smem = (40 * RPAD + 40 * TPAD) * (int)sizeof(float);  // ~87.2 KB
    cudaFuncSetAttribute(k2_conv, cudaFuncAttributeMaxDynamicSharedMemorySize, smem);
    k2_conv<<<(T + TT - 1) / TT, dim3(20, 16), smem>>>(out, T);
}